// round 8
// baseline (speedup 1.0000x reference)
#include <cuda_runtime.h>
#include <cstdint>
#include <cstddef>

// L1 attention: out[b,s,t,h] = -(1/sqrt(D)) * sum_d |q[b,s,h,d] - k[b,t,h,d]|
// B=2, S=2048, H=8, D=32. Output [b,s,t,h].
//
// Inner unit (one packed d-pair): add.rn.f32x2 (fma pipe) + and.b64 (2 LOP3,
// alu pipe) + add.rn.f32x2 (fma). -k stored in SMEM so diff is one packed add.
// Pipe floor: 4 cyc/pair/SMSP (fma and alu in parallel) ~= 119us.
//
// R8 vs R7 (203us): counter accounting showed ~1000 EXTRA instructions/warp
// (151M issued vs 87M counted) = ~4 MOVs per inner unit, caused by separate
// asm statements with distinct 64-bit temporaries (register-pair shuffling).
// Fix: ONE asm block per unit, single .b64 temp, "+l" in-place accumulator.
// k fringe in two halves of 4 (regs ~100, no spill at 2 CTAs/SM).

namespace {
constexpr int Bc  = 2;
constexpr int Sc  = 2048;
constexpr int Hc  = 8;
constexpr int Dc  = 32;
constexpr int SB  = 32;              // s rows per block
constexpr int TB  = 32;              // t cols per block
constexpr int NQ  = 8;               // 16B chunks per (s,h) row
constexpr int QROWS = SB * Hc;       // 256
constexpr int KROWS = TB * Hc;       // 256
constexpr int QST = QROWS + 1;       // 257 (16B units)
constexpr int KST = KROWS + 1;       // 257
constexpr int SMEM_U128 = NQ * QST + NQ * KST;   // 4112
}

__global__ void __launch_bounds__(256, 2)
l1attn_kernel(const float* __restrict__ qg_, const float* __restrict__ kg_,
              float* __restrict__ out) {
    extern __shared__ ulonglong2 sm[];
    ulonglong2* qs = sm;               // [NQ][QST]
    ulonglong2* ks = sm + NQ * QST;    // [NQ][KST]  (negated k)

    const int tid = threadIdx.x;
    const int b   = blockIdx.z;
    const int s0  = blockIdx.y * SB;
    const int t0  = blockIdx.x * TB;

    const float4* qg = reinterpret_cast<const float4*>(qg_ + (size_t)(b * Sc + s0) * Hc * Dc);
    const float4* kg = reinterpret_cast<const float4*>(kg_ + (size_t)(b * Sc + t0) * Hc * Dc);

    // Fill: 2048 float4 per tile, 8/thread each. g = row*8 + c -> [c][row].
    #pragma unroll
    for (int i = 0; i < (QROWS * NQ) / 256; i++) {
        int g = tid + i * 256;
        int r = g >> 3;
        int c = g & 7;
        float4 v = qg[g];
        reinterpret_cast<float4&>(qs[c * QST + r]) = v;
        float4 w = kg[g];
        w.x = -w.x; w.y = -w.y; w.z = -w.z; w.w = -w.w;
        reinterpret_cast<float4&>(ks[c * KST + r]) = w;
    }
    __syncthreads();

    // Mapping: h = tid&7, tq = (tid>>3)&3, warp sw = tid>>5.
    // Thread tile: 4 s (sw + 8*ii) x 8 t (tq + 4*jj), fixed h.
    const int h  = tid & 7;
    const int tq = (tid >> 3) & 3;
    const int sw = tid >> 5;
    const int qoff = sw * 8 + h;     // + 64*ii
    const int koff = tq * 8 + h;     // + 32*jj

    unsigned long long acc[4][8];
    #pragma unroll
    for (int ii = 0; ii < 4; ii++)
        #pragma unroll
        for (int jj = 0; jj < 8; jj++)
            acc[ii][jj] = 0ull;

    const unsigned long long ABSMASK = 0x7FFFFFFF7FFFFFFFULL;

    // One packed-pair unit, fully fused: no cross-asm temporaries, in-place
    // accumulator -> exactly 4 SASS instrs (FADD2, LOP3, LOP3, FADD2).
#define L1_UNIT(QV, KV, AC)                                                  \
    asm("{\n\t"                                                              \
        ".reg .b64 d_;\n\t"                                                  \
        "add.rn.f32x2 d_, %1, %2;\n\t"                                       \
        "and.b64 d_, d_, %3;\n\t"                                            \
        "add.rn.f32x2 %0, %0, d_;\n\t"                                       \
        "}"                                                                  \
        : "+l"(AC) : "l"(QV), "l"(KV), "l"(ABSMASK))

    #pragma unroll
    for (int c = 0; c < NQ; c++) {            // each c = 4 d's (2 packed pairs)
        const ulonglong2* qrow = qs + c * QST;
        const ulonglong2* krow = ks + c * KST;
        ulonglong2 q2[4];
        #pragma unroll
        for (int ii = 0; ii < 4; ii++) q2[ii] = qrow[qoff + 64 * ii];

        #pragma unroll
        for (int half = 0; half < 2; half++) {   // k fringe split: lower reg peak
            ulonglong2 k2[4];
            #pragma unroll
            for (int j = 0; j < 4; j++) k2[j] = krow[koff + 32 * (half * 4 + j)];
            #pragma unroll
            for (int ii = 0; ii < 4; ii++) {
                #pragma unroll
                for (int j = 0; j < 4; j++) {
                    L1_UNIT(q2[ii].x, k2[j].x, acc[ii][half * 4 + j]);
                    L1_UNIT(q2[ii].y, k2[j].y, acc[ii][half * 4 + j]);
                }
            }
        }
    }
#undef L1_UNIT

    // Epilogue: per (ii,jj) a warp covers 32 consecutive floats over (t,h).
    const float nscale = -0.17677669529663687f;  // -1/sqrt(32)
    #pragma unroll
    for (int ii = 0; ii < 4; ii++) {
        int s = s0 + sw + 8 * ii;
        size_t rowbase = ((size_t)b * Sc + s) * (size_t)Sc;
        #pragma unroll
        for (int jj = 0; jj < 8; jj++) {
            int t = t0 + tq + 4 * jj;
            float2 a = reinterpret_cast<float2&>(acc[ii][jj]);
            out[(rowbase + t) * Hc + h] = (a.x + a.y) * nscale;
        }
    }
}

extern "C" void kernel_launch(void* const* d_in, const int* in_sizes, int n_in,
                              void* d_out, int out_size) {
    const float* q = (const float*)d_in[0];
    const float* k = (const float*)d_in[1];
    float* out = (float*)d_out;

    const int smem_bytes = SMEM_U128 * (int)sizeof(ulonglong2);  // 65792
    cudaFuncSetAttribute(l1attn_kernel,
                         cudaFuncAttributeMaxDynamicSharedMemorySize, smem_bytes);

    dim3 grid(Sc / TB, Sc / SB, Bc);   // (64, 64, 2)
    l1attn_kernel<<<grid, 256, smem_bytes>>>(q, k, out);
}